// round 14
// baseline (speedup 1.0000x reference)
#include <cuda_runtime.h>

// N=8192 rows, C=5000 classes, RATIO=3
#define NC    5000
#define NT    256
#define NW    8
#define NV4   1250          // float4 per row
#define CAP   768           // list / candidate capacity
#define NBF   512           // fast-path fine bins
#define PIVF  1.5f
#define PB    0x3FC00000u   // bits of 1.5f

__device__ double   g_loss = 0.0;
__device__ double   g_tsum = 0.0;
__device__ unsigned g_done = 0;

__device__ __forceinline__ unsigned fkey(float f) {        // fallback only
    unsigned b = __float_as_uint(f);
    return (b & 0x80000000u) ? ~b : (b | 0x80000000u);
}
__device__ __forceinline__ float kinv(unsigned k) {
    return __uint_as_float((k & 0x80000000u) ? (k & 0x7FFFFFFFu) : ~k);
}
__device__ __forceinline__ float sp(float x) {
    float l = __logf(1.f + __expf(-fabsf(x)));
    return x > 0.f ? x + l : l;
}
__device__ __forceinline__ unsigned fbin(unsigned b) {     // raw positive-float bits
    unsigned v = (b - PB) >> 19;
    return v > (NBF - 1) ? (NBF - 1) : v;
}

__global__ void __launch_bounds__(NT, 4)
hardneg(const float* __restrict__ pred, const float* __restrict__ target,
        float* __restrict__ out)
{
    __shared__ unsigned s_hist[2048];  // fast path uses [0,512); fallback uses all (packed)
    __shared__ unsigned s_list[CAP];
    __shared__ unsigned s_cand[CAP];
    __shared__ unsigned s_wsum[NW];
    __shared__ int      s_posr[NW];
    __shared__ float    s_accr[NW];
    __shared__ unsigned s_binv, s_kkv, s_tkey, s_krem;
    __shared__ int      s_cnt, s_ccnt;

    const int tid  = threadIdx.x;
    const int lane = tid & 31;
    const int wid  = tid >> 5;
    const int row  = blockIdx.x;

    const float*  prow = pred   + (size_t)row * NC;
    const float*  trow = target + (size_t)row * NC;
    const float4* p4 = (const float4*)prow;
    const float4* t4 = (const float4*)trow;

    if (tid < 128) ((uint4*)s_hist)[tid] = make_uint4(0, 0, 0, 0);
    if (tid == 0) { s_cnt = 0; s_ccnt = 0; }

    // ======== front-batched loads: 10 LDG.128 in flight (MLP=10) ========
    float4 pr[5], tr[5];
    #pragma unroll
    for (int j = 0; j < 5; j++) {
        int i  = j * NT + tid;
        int ic = (j < 4 || i < NV4) ? i : 0;   // clamped dup load on tail (harmless)
        pr[j] = __ldcs(&p4[ic]);
        tr[j] = __ldcs(&t4[ic]);
    }
    __syncthreads();   // covers the zeroing above

    // ======== process: float-gate push (raw bits) + rare positive BCE ========
    int   poscnt = 0;
    float accP   = 0.f;

    #define PROC(px, tx)                                                    \
        do {                                                                \
            float _x = (px);                                                \
            if ((tx) != 0.f) {                                              \
                poscnt++; accP += sp(-_x);                                  \
            } else if (_x > PIVF) {                                         \
                int _s = atomicAdd(&s_cnt, 1);                              \
                if (_s < CAP) s_list[_s] = __float_as_uint(_x);             \
            }                                                               \
        } while (0)

    #pragma unroll
    for (int j = 0; j < 5; j++) {
        int i = j * NT + tid;
        if (j < 4 || i < NV4) {
            PROC(pr[j].x, tr[j].x);
            PROC(pr[j].y, tr[j].y);
            PROC(pr[j].z, tr[j].z);
            PROC(pr[j].w, tr[j].w);
        }
    }
    #undef PROC

    int pc = poscnt;
    #pragma unroll
    for (int off = 16; off; off >>= 1) pc += __shfl_down_sync(0xFFFFFFFFu, pc, off);
    if (lane == 0) s_posr[wid] = pc;
    __syncthreads();

    int post = 0;
    #pragma unroll
    for (int w = 0; w < NW; w++) post += s_posr[w];
    int k0 = 3 * post;
    if (k0 > NC - post) k0 = NC - post;
    const unsigned kk = (unsigned)k0;

    const int  cnt  = s_cnt;
    const bool fast = (cnt >= k0) && (cnt <= CAP);
    float acc = accP;

    if (k0 > 0 && fast) {
        // ---- histogram of the list (512 fine offset bins over raw bits) ----
        for (int i = tid; i < cnt; i += NT)
            atomicAdd(&s_hist[fbin(s_list[i])], 1u);
        __syncthreads();

        // ---- suffix scan: thread owns 2 bins ----
        unsigned w2[2];
        unsigned S = 0;
        #pragma unroll
        for (int j = 0; j < 2; j++) { w2[j] = s_hist[tid * 2 + j]; S += w2[j]; }
        unsigned v = S;
        #pragma unroll
        for (int off = 1; off < 32; off <<= 1) {
            unsigned o = __shfl_down_sync(0xFFFFFFFFu, v, off);
            if (lane + off < 32) v += o;
        }
        if (lane == 0) s_wsum[wid] = v;
        __syncthreads();

        unsigned above = v - S;
        #pragma unroll
        for (int w = wid + 1; w < NW; w++) above += s_wsum[w];
        if (above < kk && kk <= above + S) {
            unsigned a = above;
            #pragma unroll
            for (int j = 1; j >= 0; j--) {
                unsigned c = w2[j];
                if (kk <= a + c) { s_binv = (unsigned)(tid * 2 + j); s_kkv = kk - a; break; }
                a += c;
            }
        }
        __syncthreads();

        // ---- list scan: above-bin softplus + gather threshold-bin candidates ----
        const unsigned bv = s_binv;
        for (int i = tid; i < cnt; i += NT) {
            unsigned key = s_list[i];
            unsigned b   = fbin(key);
            if (b > bv) acc += sp(__uint_as_float(key));
            else if (b == bv) {
                int s = atomicAdd(&s_ccnt, 1);
                if (s < CAP) s_cand[s] = key;
            }
        }
    } else if (k0 > 0) {
        // ======== cold exact fallback (packed 4096-bin fkey histogram) ========
        ((uint4*)s_hist)[tid]      = make_uint4(0, 0, 0, 0);
        ((uint4*)s_hist)[tid + NT] = make_uint4(0, 0, 0, 0);
        __syncthreads();
        for (int i = tid; i < NC; i += NT) {
            if (trow[i] == 0.f) {
                unsigned k = fkey(prow[i]);
                atomicAdd(&s_hist[k >> 21], ((k >> 20) & 1u) ? 65536u : 1u);
            }
        }
        __syncthreads();

        unsigned w8[8];
        unsigned S = 0;
        #pragma unroll
        for (int j = 0; j < 8; j++) {
            unsigned vv = s_hist[tid * 8 + j];
            w8[j] = vv;
            S += (vv & 0xFFFFu) + (vv >> 16);
        }
        unsigned v = S;
        #pragma unroll
        for (int off = 1; off < 32; off <<= 1) {
            unsigned o = __shfl_down_sync(0xFFFFFFFFu, v, off);
            if (lane + off < 32) v += o;
        }
        if (lane == 0) s_wsum[wid] = v;
        __syncthreads();

        unsigned above = v - S;
        #pragma unroll
        for (int w = wid + 1; w < NW; w++) above += s_wsum[w];
        if (above < kk && kk <= above + S) {
            unsigned a = above;
            #pragma unroll
            for (int j = 15; j >= 0; j--) {
                unsigned wv = w8[j >> 1];
                unsigned c  = (j & 1) ? (wv >> 16) : (wv & 0xFFFFu);
                if (kk <= a + c) { s_binv = (unsigned)(tid * 16 + j); s_kkv = kk - a; break; }
                a += c;
            }
        }
        __syncthreads();

        const unsigned bv = s_binv;
        for (int i = tid; i < NC; i += NT) {
            if (trow[i] == 0.f) {
                unsigned k = fkey(prow[i]);
                unsigned b = k >> 20;
                if (b > bv) acc += sp(kinv(k));
                else if (b == bv) {
                    int s = atomicAdd(&s_ccnt, 1);
                    if (s < CAP) s_cand[s] = k;
                }
            }
        }
    }
    __syncthreads();

    // ======== exact k-th largest among candidates (rank counting) ========
    if (k0 > 0) {
        int M = s_ccnt; if (M > CAP) M = CAP;
        const unsigned kk2 = s_kkv;
        for (int c = tid; c < M; c += NT) {
            unsigned key = s_cand[c];
            unsigned gt = 0, eq = 0;
            for (int j = 0; j < M; j++) {
                unsigned o = s_cand[j];
                gt += (o > key);
                eq += (o == key);
            }
            if (gt < kk2 && kk2 <= gt + eq) { s_tkey = key; s_krem = kk2 - gt; }
        }
    }
    __syncthreads();

    if (k0 > 0) {
        const unsigned tk = s_tkey;
        int M = s_ccnt; if (M > CAP) M = CAP;
        for (int c = tid; c < M; c += NT) {
            unsigned key = s_cand[c];
            if (key > tk) acc += sp(fast ? __uint_as_float(key) : kinv(key));
        }
    }

    // ======== block reduce + global accumulate + last-block finalize ========
    #pragma unroll
    for (int off = 16; off; off >>= 1) acc += __shfl_down_sync(0xFFFFFFFFu, acc, off);
    if (lane == 0) s_accr[wid] = acc;
    __syncthreads();

    if (tid == 0) {
        float totL = 0.f;
        #pragma unroll
        for (int w = 0; w < NW; w++) totL += s_accr[w];
        if (k0 > 0) {
            float tval = fast ? __uint_as_float(s_tkey) : kinv(s_tkey);
            totL += (float)s_krem * sp(tval);   // exact tie correction
        }
        atomicAdd(&g_loss, (double)totL);
        atomicAdd(&g_tsum, (double)post);
        __threadfence();
        unsigned done = atomicAdd(&g_done, 1u);
        if (done == gridDim.x - 1) {
            double L = atomicAdd(&g_loss, 0.0);
            double T = atomicAdd(&g_tsum, 0.0);
            out[0] = (float)(L / T);
            atomicExch((unsigned long long*)&g_loss, 0ull);
            atomicExch((unsigned long long*)&g_tsum, 0ull);
            __threadfence();
            atomicExch(&g_done, 0u);
        }
    }
}

extern "C" void kernel_launch(void* const* d_in, const int* in_sizes, int n_in,
                              void* d_out, int out_size) {
    const float* pred   = (const float*)d_in[0];
    const float* target = (const float*)d_in[1];
    float* out = (float*)d_out;
    int rows = in_sizes[0] / NC;

    hardneg<<<rows, NT>>>(pred, target, out);
}

// round 15
// speedup vs baseline: 1.1524x; 1.1524x over previous
#include <cuda_runtime.h>

// N=8192 rows, C=5000 classes, RATIO=3
#define NC    5000
#define NT    256
#define NW    8
#define NV4   1250          // float4 per row
#define SLOTS 8             // per-thread push slots
#define CAP   768           // candidate capacity
#define NBF   512           // fast-path fine bins
#define PIVF  1.5f
#define PB    0x3FC00000u   // bits of 1.5f

__device__ double   g_loss = 0.0;
__device__ double   g_tsum = 0.0;
__device__ unsigned g_done = 0;

__device__ __forceinline__ unsigned fkey(float f) {        // fallback only
    unsigned b = __float_as_uint(f);
    return (b & 0x80000000u) ? ~b : (b | 0x80000000u);
}
__device__ __forceinline__ float kinv(unsigned k) {
    return __uint_as_float((k & 0x80000000u) ? (k & 0x7FFFFFFFu) : ~k);
}
__device__ __forceinline__ float sp(float x) {
    float l = __logf(1.f + __expf(-fabsf(x)));
    return x > 0.f ? x + l : l;
}
__device__ __forceinline__ unsigned fbin(unsigned b) {     // raw positive-float bits
    unsigned v = (b - PB) >> 19;
    return v > (NBF - 1) ? (NBF - 1) : v;
}

__global__ void __launch_bounds__(NT)
hardneg(const float* __restrict__ pred, const float* __restrict__ target,
        float* __restrict__ out)
{
    __shared__ unsigned s_hist[2048];        // fast: [0,512); fallback: packed 4096 bins
    __shared__ unsigned s_slot[SLOTS * NT];  // 8KB, slot-major: conflict-free per thread
    __shared__ unsigned s_cand[CAP];
    __shared__ unsigned s_wsum[NW];
    __shared__ unsigned s_posr[NW];          // packed: poscnt | pushcnt<<16
    __shared__ int      s_mxr[NW];           // max per-thread push count
    __shared__ float    s_accr[NW];
    __shared__ unsigned s_binv, s_kkv, s_tkey, s_krem;
    __shared__ int      s_ccnt;

    const int tid  = threadIdx.x;
    const int lane = tid & 31;
    const int wid  = tid >> 5;
    const int row  = blockIdx.x;

    const float*  prow = pred   + (size_t)row * NC;
    const float*  trow = target + (size_t)row * NC;
    const float4* p4 = (const float4*)prow;
    const float4* t4 = (const float4*)trow;

    if (tid < 128) ((uint4*)s_hist)[tid] = make_uint4(0, 0, 0, 0);
    if (tid == 0) s_ccnt = 0;
    __syncthreads();

    // ======== hot pass: float-gate push to PRIVATE slots (no atomics) ========
    int   poscnt = 0;
    int   mycnt  = 0;
    float accP   = 0.f;

    #define PROC(px, tx)                                                    \
        do {                                                                \
            float _x = (px);                                                \
            if ((tx) != 0.f) {                                              \
                poscnt++; accP += sp(-_x);                                  \
            } else if (_x > PIVF) {                                         \
                if (mycnt < SLOTS)                                          \
                    s_slot[mycnt * NT + tid] = __float_as_uint(_x);         \
                mycnt++;                                                    \
            }                                                               \
        } while (0)

    #pragma unroll
    for (int j = 0; j < 5; j++) {
        int i = j * NT + tid;
        if (j < 4 || i < NV4) {
            float4 p = __ldcs(&p4[i]);
            float4 t = __ldcs(&t4[i]);
            PROC(p.x, t.x);
            PROC(p.y, t.y);
            PROC(p.z, t.z);
            PROC(p.w, t.w);
        }
    }
    #undef PROC

    // packed reduce: poscnt (lo16) + pushcnt (hi16); separate max of mycnt
    unsigned pA = (unsigned)poscnt | ((unsigned)mycnt << 16);
    int      mx = mycnt;
    #pragma unroll
    for (int off = 16; off; off >>= 1) {
        pA += __shfl_down_sync(0xFFFFFFFFu, pA, off);
        int o = __shfl_down_sync(0xFFFFFFFFu, mx, off);
        mx = o > mx ? o : mx;
    }
    if (lane == 0) { s_posr[wid] = pA; s_mxr[wid] = mx; }
    __syncthreads();

    unsigned tot = 0;
    int      mxa = 0;
    #pragma unroll
    for (int w = 0; w < NW; w++) {
        tot += s_posr[w];
        int m = s_mxr[w];
        mxa = m > mxa ? m : mxa;
    }
    const int post = (int)(tot & 0xFFFFu);
    const int cnt  = (int)(tot >> 16);
    int k0 = 3 * post;
    if (k0 > NC - post) k0 = NC - post;
    const unsigned kk = (unsigned)k0;

    const bool fast = (cnt >= k0) && (mxa <= SLOTS);
    const int  myn  = mycnt < SLOTS ? mycnt : SLOTS;
    float acc = accP;

    if (k0 > 0 && fast) {
        // ---- histogram from private slots (sparse atomics, ~330 total) ----
        for (int i = 0; i < myn; i++)
            atomicAdd(&s_hist[fbin(s_slot[i * NT + tid])], 1u);
        __syncthreads();

        // ---- suffix scan: thread owns 2 bins ----
        unsigned w2[2];
        unsigned S = 0;
        #pragma unroll
        for (int j = 0; j < 2; j++) { w2[j] = s_hist[tid * 2 + j]; S += w2[j]; }
        unsigned v = S;
        #pragma unroll
        for (int off = 1; off < 32; off <<= 1) {
            unsigned o = __shfl_down_sync(0xFFFFFFFFu, v, off);
            if (lane + off < 32) v += o;
        }
        if (lane == 0) s_wsum[wid] = v;
        __syncthreads();

        unsigned above = v - S;
        #pragma unroll
        for (int w = wid + 1; w < NW; w++) above += s_wsum[w];
        if (above < kk && kk <= above + S) {
            unsigned a = above;
            #pragma unroll
            for (int j = 1; j >= 0; j--) {
                unsigned c = w2[j];
                if (kk <= a + c) { s_binv = (unsigned)(tid * 2 + j); s_kkv = kk - a; break; }
                a += c;
            }
        }
        __syncthreads();

        // ---- slot scan: above-bin softplus + gather threshold-bin candidates ----
        const unsigned bv = s_binv;
        for (int i = 0; i < myn; i++) {
            unsigned key = s_slot[i * NT + tid];
            unsigned b   = fbin(key);
            if (b > bv) acc += sp(__uint_as_float(key));
            else if (b == bv) {
                int s = atomicAdd(&s_ccnt, 1);
                if (s < CAP) s_cand[s] = key;
            }
        }
    } else if (k0 > 0) {
        // ======== cold exact fallback (packed 4096-bin fkey histogram) ========
        ((uint4*)s_hist)[tid]      = make_uint4(0, 0, 0, 0);
        ((uint4*)s_hist)[tid + NT] = make_uint4(0, 0, 0, 0);
        __syncthreads();
        for (int i = tid; i < NC; i += NT) {
            if (trow[i] == 0.f) {
                unsigned k = fkey(prow[i]);
                atomicAdd(&s_hist[k >> 21], ((k >> 20) & 1u) ? 65536u : 1u);
            }
        }
        __syncthreads();

        unsigned w8[8];
        unsigned S = 0;
        #pragma unroll
        for (int j = 0; j < 8; j++) {
            unsigned vv = s_hist[tid * 8 + j];
            w8[j] = vv;
            S += (vv & 0xFFFFu) + (vv >> 16);
        }
        unsigned v = S;
        #pragma unroll
        for (int off = 1; off < 32; off <<= 1) {
            unsigned o = __shfl_down_sync(0xFFFFFFFFu, v, off);
            if (lane + off < 32) v += o;
        }
        if (lane == 0) s_wsum[wid] = v;
        __syncthreads();

        unsigned above = v - S;
        #pragma unroll
        for (int w = wid + 1; w < NW; w++) above += s_wsum[w];
        if (above < kk && kk <= above + S) {
            unsigned a = above;
            #pragma unroll
            for (int j = 15; j >= 0; j--) {
                unsigned wv = w8[j >> 1];
                unsigned c  = (j & 1) ? (wv >> 16) : (wv & 0xFFFFu);
                if (kk <= a + c) { s_binv = (unsigned)(tid * 16 + j); s_kkv = kk - a; break; }
                a += c;
            }
        }
        __syncthreads();

        const unsigned bv = s_binv;
        for (int i = tid; i < NC; i += NT) {
            if (trow[i] == 0.f) {
                unsigned k = fkey(prow[i]);
                unsigned b = k >> 20;
                if (b > bv) acc += sp(kinv(k));
                else if (b == bv) {
                    int s = atomicAdd(&s_ccnt, 1);
                    if (s < CAP) s_cand[s] = k;
                }
            }
        }
    }
    __syncthreads();

    // ======== exact k-th largest among candidates (rank counting) ========
    if (k0 > 0) {
        int M = s_ccnt; if (M > CAP) M = CAP;
        const unsigned kk2 = s_kkv;
        for (int c = tid; c < M; c += NT) {
            unsigned key = s_cand[c];
            unsigned gt = 0, eq = 0;
            for (int j = 0; j < M; j++) {
                unsigned o = s_cand[j];
                gt += (o > key);
                eq += (o == key);
            }
            if (gt < kk2 && kk2 <= gt + eq) { s_tkey = key; s_krem = kk2 - gt; }
        }
    }
    __syncthreads();

    if (k0 > 0) {
        const unsigned tk = s_tkey;
        int M = s_ccnt; if (M > CAP) M = CAP;
        for (int c = tid; c < M; c += NT) {
            unsigned key = s_cand[c];
            if (key > tk) acc += sp(fast ? __uint_as_float(key) : kinv(key));
        }
    }

    // ======== block reduce + global accumulate + last-block finalize ========
    #pragma unroll
    for (int off = 16; off; off >>= 1) acc += __shfl_down_sync(0xFFFFFFFFu, acc, off);
    if (lane == 0) s_accr[wid] = acc;
    __syncthreads();

    if (tid == 0) {
        float totL = 0.f;
        #pragma unroll
        for (int w = 0; w < NW; w++) totL += s_accr[w];
        if (k0 > 0) {
            float tval = fast ? __uint_as_float(s_tkey) : kinv(s_tkey);
            totL += (float)s_krem * sp(tval);   // exact tie correction
        }
        atomicAdd(&g_loss, (double)totL);
        atomicAdd(&g_tsum, (double)post);
        __threadfence();
        unsigned done = atomicAdd(&g_done, 1u);
        if (done == gridDim.x - 1) {
            double L = atomicAdd(&g_loss, 0.0);
            double T = atomicAdd(&g_tsum, 0.0);
            out[0] = (float)(L / T);
            atomicExch((unsigned long long*)&g_loss, 0ull);
            atomicExch((unsigned long long*)&g_tsum, 0ull);
            __threadfence();
            atomicExch(&g_done, 0u);
        }
    }
}

extern "C" void kernel_launch(void* const* d_in, const int* in_sizes, int n_in,
                              void* d_out, int out_size) {
    const float* pred   = (const float*)d_in[0];
    const float* target = (const float*)d_in[1];
    float* out = (float*)d_out;
    int rows = in_sizes[0] / NC;

    hardneg<<<rows, NT>>>(pred, target, out);
}

// round 16
// speedup vs baseline: 1.3230x; 1.1480x over previous
#include <cuda_runtime.h>

// N=8192 rows, C=5000 classes, RATIO=3
#define NC    5000
#define NT    256
#define NW    8
#define NV4   1250          // float4 per row
#define CAPL  512           // per-row list / candidate capacity
#define NBF   512           // fine bins per row
#define PIVF  1.5f
#define PB    0x3FC00000u   // bits of 1.5f

__device__ double   g_loss = 0.0;
__device__ double   g_tsum = 0.0;
__device__ unsigned g_done = 0;

__device__ __forceinline__ unsigned fkey(float f) {        // fallback only
    unsigned b = __float_as_uint(f);
    return (b & 0x80000000u) ? ~b : (b | 0x80000000u);
}
__device__ __forceinline__ float kinv(unsigned k) {
    return __uint_as_float((k & 0x80000000u) ? (k & 0x7FFFFFFFu) : ~k);
}
__device__ __forceinline__ float sp(float x) {
    float l = __logf(1.f + __expf(-fabsf(x)));
    return x > 0.f ? x + l : l;
}
__device__ __forceinline__ unsigned fbin(unsigned b) {     // raw positive-float bits
    unsigned v = (b - PB) >> 19;
    return v > (NBF - 1) ? (NBF - 1) : v;
}

__global__ void __launch_bounds__(NT)
hardneg(const float* __restrict__ pred, const float* __restrict__ target,
        float* __restrict__ out, int rows)
{
    __shared__ unsigned s_hist[2048];   // fast: A=[0,512) B=[512,1024); fallback: all
    __shared__ unsigned s_lista[CAPL];
    __shared__ unsigned s_listb[CAPL];
    __shared__ unsigned s_cand[CAPL];
    __shared__ unsigned s_wsum[NW];
    __shared__ unsigned s_posr[NW];     // packed posA | posB<<16
    __shared__ float    s_accr[NW];
    __shared__ unsigned s_binv, s_kkv, s_tkey, s_krem;
    __shared__ int      s_cnta, s_cntb, s_ccnt;

    const int tid  = threadIdx.x;
    const int lane = tid & 31;
    const int wid  = tid >> 5;
    const int rowA = 2 * blockIdx.x;
    const int rowB = rowA + 1;
    const bool hasB = (rowB < rows);

    const float*  prowA = pred   + (size_t)rowA * NC;
    const float*  trowA = target + (size_t)rowA * NC;
    const float*  prowB = hasB ? (prowA + NC) : prowA;
    const float*  trowB = hasB ? (trowA + NC) : trowA;
    const float4* pa4 = (const float4*)prowA;
    const float4* ta4 = (const float4*)trowA;
    const float4* pb4 = (const float4*)prowB;
    const float4* tb4 = (const float4*)trowB;

    ((uint4*)s_hist)[tid] = make_uint4(0, 0, 0, 0);   // zero [0,1024) words
    if (tid == 0) { s_cnta = 0; s_cntb = 0; s_ccnt = 0; }
    __syncthreads();

    // ======== hot pass: interleaved two-row stream (4 LDG.128 in flight) ========
    int   posA = 0, posB = 0;
    float acc  = 0.f;

    #define PROCX(px, tx, pcnt, cntp, listp)                                \
        do {                                                                \
            float _x = (px);                                                \
            if ((tx) != 0.f) {                                              \
                pcnt++; acc += sp(-_x);                                     \
            } else if (_x > PIVF) {                                         \
                int _s = atomicAdd(cntp, 1);                                \
                if (_s < CAPL) (listp)[_s] = __float_as_uint(_x);           \
            }                                                               \
        } while (0)

    #pragma unroll
    for (int j = 0; j < 5; j++) {
        int i = j * NT + tid;
        if (j < 4 || i < NV4) {
            float4 pa = __ldcs(&pa4[i]);
            float4 ta = __ldcs(&ta4[i]);
            float4 pb = __ldcs(&pb4[i]);
            float4 tb = __ldcs(&tb4[i]);
            PROCX(pa.x, ta.x, posA, &s_cnta, s_lista);
            PROCX(pa.y, ta.y, posA, &s_cnta, s_lista);
            PROCX(pa.z, ta.z, posA, &s_cnta, s_lista);
            PROCX(pa.w, ta.w, posA, &s_cnta, s_lista);
            if (hasB) {
                PROCX(pb.x, tb.x, posB, &s_cntb, s_listb);
                PROCX(pb.y, tb.y, posB, &s_cntb, s_listb);
                PROCX(pb.z, tb.z, posB, &s_cntb, s_listb);
                PROCX(pb.w, tb.w, posB, &s_cntb, s_listb);
            }
        }
    }
    #undef PROCX

    unsigned pk = (unsigned)posA | ((unsigned)posB << 16);
    #pragma unroll
    for (int off = 16; off; off >>= 1) pk += __shfl_down_sync(0xFFFFFFFFu, pk, off);
    if (lane == 0) s_posr[wid] = pk;
    __syncthreads();

    unsigned tot = 0;
    #pragma unroll
    for (int w = 0; w < NW; w++) tot += s_posr[w];
    const int postA = (int)(tot & 0xFFFFu);
    const int postB = (int)(tot >> 16);

    // ================== per-row selection (A then B) ==================
    #define SELECT_ROW(post, cntv, listv, HOFF, prow, trow)                      \
    {                                                                            \
        int k0 = 3 * (post);                                                     \
        if (k0 > NC - (post)) k0 = NC - (post);                                  \
        const unsigned kk = (unsigned)k0;                                        \
        const int  cnt  = (cntv);                                                \
        const bool fast = (cnt >= k0) && (cnt <= CAPL);                          \
        if (k0 > 0 && fast) {                                                    \
            for (int i = tid; i < cnt; i += NT)                                  \
                atomicAdd(&s_hist[(HOFF) + fbin((listv)[i])], 1u);               \
            __syncthreads();                                                     \
            unsigned w2[2];                                                      \
            unsigned S = 0;                                                      \
            w2[0] = s_hist[(HOFF) + tid * 2];                                    \
            w2[1] = s_hist[(HOFF) + tid * 2 + 1];                                \
            S = w2[0] + w2[1];                                                   \
            unsigned v = S;                                                      \
            _Pragma("unroll")                                                    \
            for (int off = 1; off < 32; off <<= 1) {                             \
                unsigned o = __shfl_down_sync(0xFFFFFFFFu, v, off);              \
                if (lane + off < 32) v += o;                                     \
            }                                                                    \
            if (lane == 0) s_wsum[wid] = v;                                      \
            __syncthreads();                                                     \
            unsigned above = v - S;                                              \
            _Pragma("unroll")                                                    \
            for (int w = wid + 1; w < NW; w++) above += s_wsum[w];               \
            if (above < kk && kk <= above + S) {                                 \
                unsigned a = above;                                              \
                if (kk <= a + w2[1]) { s_binv = (unsigned)(tid*2+1); s_kkv = kk - a; } \
                else { a += w2[1]; s_binv = (unsigned)(tid*2); s_kkv = kk - a; } \
            }                                                                    \
            __syncthreads();                                                     \
            const unsigned bv = s_binv;                                          \
            for (int i = tid; i < cnt; i += NT) {                                \
                unsigned key = (listv)[i];                                       \
                unsigned b   = fbin(key);                                        \
                if (b > bv) acc += sp(__uint_as_float(key));                     \
                else if (b == bv) {                                              \
                    int s = atomicAdd(&s_ccnt, 1);                               \
                    if (s < CAPL) s_cand[s] = key;                               \
                }                                                                \
            }                                                                    \
        } else if (k0 > 0) {                                                     \
            /* exact fallback: packed 4096-bin fkey histogram, global reread */  \
            ((uint4*)s_hist)[tid]      = make_uint4(0, 0, 0, 0);                 \
            ((uint4*)s_hist)[tid + NT] = make_uint4(0, 0, 0, 0);                 \
            __syncthreads();                                                     \
            for (int i = tid; i < NC; i += NT) {                                 \
                if ((trow)[i] == 0.f) {                                          \
                    unsigned k = fkey((prow)[i]);                                \
                    atomicAdd(&s_hist[k >> 21], ((k >> 20) & 1u) ? 65536u : 1u); \
                }                                                                \
            }                                                                    \
            __syncthreads();                                                     \
            unsigned w8[8];                                                      \
            unsigned S = 0;                                                      \
            _Pragma("unroll")                                                    \
            for (int j = 0; j < 8; j++) {                                        \
                unsigned vv = s_hist[tid * 8 + j];                               \
                w8[j] = vv;                                                      \
                S += (vv & 0xFFFFu) + (vv >> 16);                                \
            }                                                                    \
            unsigned v = S;                                                      \
            _Pragma("unroll")                                                    \
            for (int off = 1; off < 32; off <<= 1) {                             \
                unsigned o = __shfl_down_sync(0xFFFFFFFFu, v, off);              \
                if (lane + off < 32) v += o;                                     \
            }                                                                    \
            if (lane == 0) s_wsum[wid] = v;                                      \
            __syncthreads();                                                     \
            unsigned above = v - S;                                              \
            _Pragma("unroll")                                                    \
            for (int w = wid + 1; w < NW; w++) above += s_wsum[w];               \
            if (above < kk && kk <= above + S) {                                 \
                unsigned a = above;                                              \
                _Pragma("unroll")                                                \
                for (int j = 15; j >= 0; j--) {                                  \
                    unsigned wv = w8[j >> 1];                                    \
                    unsigned c  = (j & 1) ? (wv >> 16) : (wv & 0xFFFFu);         \
                    if (kk <= a + c) { s_binv = (unsigned)(tid*16+j); s_kkv = kk - a; break; } \
                    a += c;                                                      \
                }                                                                \
            }                                                                    \
            __syncthreads();                                                     \
            const unsigned bv = s_binv;                                          \
            for (int i = tid; i < NC; i += NT) {                                 \
                if ((trow)[i] == 0.f) {                                          \
                    unsigned k = fkey((prow)[i]);                                \
                    unsigned b = k >> 20;                                        \
                    if (b > bv) acc += sp(kinv(k));                              \
                    else if (b == bv) {                                          \
                        int s = atomicAdd(&s_ccnt, 1);                           \
                        if (s < CAPL) s_cand[s] = k;                             \
                    }                                                            \
                }                                                                \
            }                                                                    \
        }                                                                        \
        __syncthreads();                                                         \
        if (k0 > 0) {                                                            \
            int M = s_ccnt; if (M > CAPL) M = CAPL;                              \
            const unsigned kk2 = s_kkv;                                          \
            for (int c = tid; c < M; c += NT) {                                  \
                unsigned key = s_cand[c];                                        \
                unsigned gt = 0, eq = 0;                                         \
                for (int j = 0; j < M; j++) {                                    \
                    unsigned o = s_cand[j];                                      \
                    gt += (o > key);                                             \
                    eq += (o == key);                                            \
                }                                                                \
                if (gt < kk2 && kk2 <= gt + eq) { s_tkey = key; s_krem = kk2 - gt; } \
            }                                                                    \
        }                                                                        \
        __syncthreads();                                                         \
        if (k0 > 0) {                                                            \
            const unsigned tk = s_tkey;                                          \
            int M = s_ccnt; if (M > CAPL) M = CAPL;                              \
            for (int c = tid; c < M; c += NT) {                                  \
                unsigned key = s_cand[c];                                        \
                if (key > tk) acc += sp(fast ? __uint_as_float(key) : kinv(key)); \
            }                                                                    \
            if (tid == 0) {                                                      \
                float tval = fast ? __uint_as_float(s_tkey) : kinv(s_tkey);      \
                acc += (float)s_krem * sp(tval);                                 \
            }                                                                    \
        }                                                                        \
        __syncthreads();                                                         \
    }

    // ---- row A ----
    SELECT_ROW(postA, s_cnta, s_lista, 0, prowA, trowA)

    // reset shared scratch for row B; re-zero B's bin region (dirty iff A fell back)
    if (tid == 0) s_ccnt = 0;
    if (tid < 128) ((uint4*)s_hist)[128 + tid] = make_uint4(0, 0, 0, 0);  // words [512,1024)
    __syncthreads();

    // ---- row B ----
    if (hasB) {
        SELECT_ROW(postB, s_cntb, s_listb, 512, prowB, trowB)
    }
    #undef SELECT_ROW

    // ======== block reduce + global accumulate + last-block finalize ========
    #pragma unroll
    for (int off = 16; off; off >>= 1) acc += __shfl_down_sync(0xFFFFFFFFu, acc, off);
    if (lane == 0) s_accr[wid] = acc;
    __syncthreads();

    if (tid == 0) {
        float totL = 0.f;
        #pragma unroll
        for (int w = 0; w < NW; w++) totL += s_accr[w];
        atomicAdd(&g_loss, (double)totL);
        atomicAdd(&g_tsum, (double)(postA + postB));
        __threadfence();
        unsigned done = atomicAdd(&g_done, 1u);
        if (done == gridDim.x - 1) {
            double L = atomicAdd(&g_loss, 0.0);
            double T = atomicAdd(&g_tsum, 0.0);
            out[0] = (float)(L / T);
            atomicExch((unsigned long long*)&g_loss, 0ull);
            atomicExch((unsigned long long*)&g_tsum, 0ull);
            __threadfence();
            atomicExch(&g_done, 0u);
        }
    }
}

extern "C" void kernel_launch(void* const* d_in, const int* in_sizes, int n_in,
                              void* d_out, int out_size) {
    const float* pred   = (const float*)d_in[0];
    const float* target = (const float*)d_in[1];
    float* out = (float*)d_out;
    int rows = in_sizes[0] / NC;
    int grid = (rows + 1) / 2;

    hardneg<<<grid, NT>>>(pred, target, out, rows);
}